// round 16
// baseline (speedup 1.0000x reference)
#include <cuda_runtime.h>
#include <cuda_fp16.h>
#include <cstdint>
#include <cstddef>

#define DIM   4096
#define H3    12288
#define FFN_D 16384
#define NT    2048      // total tokens = 2*1024
#define LR    16        // lora rank
#define SEQ   1024
#define NH    32
#define HD    128
#define NA    8

// ---------------- scratch (device globals; no allocations allowed) ----------
__device__ float g_res2[(size_t)NT * DIM];
__device__ float g_u   [(size_t)NT * LR];

// fp16 weight plane + fp16 activation planes
#define WOFF_QKV 0
#define WOFF_OUT 50331648u
#define WOFF_FC1 67108864u
#define WOFF_FC2 134217728u
#define W_TOTAL  201326592u
__device__ __half g_Wh [W_TOTAL];
__device__ __half g_AS [(size_t)NT * DIM];
__device__ __half g_AL [(size_t)NT * FFN_D];   // doubles as fp16 qkv plane

// fp16 lora-A planes: qkv | out | fc1 (each 8*16*4096) then fc2 (8*16*16384)
#define AOFF_QKV 0
#define AOFF_OUT 524288u
#define AOFF_FC1 1048576u
#define AOFF_FC2 1572864u
#define A_TOTAL  3670016u
__device__ __half g_Ah [A_TOTAL];

// ================= helpers ===================================================
__device__ __forceinline__ uint32_t smem_u32(const void* p) {
    uint32_t a;
    asm("{ .reg .u64 t; cvta.to.shared.u64 t, %1; cvt.u32.u64 %0, t; }"
        : "=r"(a) : "l"(p));
    return a;
}
__device__ __forceinline__ void ldmx4(uint32_t* r, uint32_t addr) {
    asm volatile("ldmatrix.sync.aligned.m8n8.x4.shared.b16 {%0,%1,%2,%3}, [%4];"
                 : "=r"(r[0]), "=r"(r[1]), "=r"(r[2]), "=r"(r[3]) : "r"(addr));
}
__device__ __forceinline__ void ldmx4t(uint32_t* r, uint32_t addr) {
    asm volatile("ldmatrix.sync.aligned.m8n8.x4.trans.shared.b16 {%0,%1,%2,%3}, [%4];"
                 : "=r"(r[0]), "=r"(r[1]), "=r"(r[2]), "=r"(r[3]) : "r"(addr));
}
__device__ __forceinline__ uint32_t lds32(uint32_t addr) {
    uint32_t v;
    asm volatile("ld.shared.b32 %0, [%1];" : "=r"(v) : "r"(addr));
    return v;
}
__device__ __forceinline__ void mmaf16(float* d, const uint32_t* a,
                                       uint32_t b0, uint32_t b1) {
    asm volatile("mma.sync.aligned.m16n8k16.row.col.f32.f16.f16.f32 "
                 "{%0,%1,%2,%3}, {%4,%5,%6,%7}, {%8,%9}, {%0,%1,%2,%3};"
                 : "+f"(d[0]), "+f"(d[1]), "+f"(d[2]), "+f"(d[3])
                 : "r"(a[0]), "r"(a[1]), "r"(a[2]), "r"(a[3]),
                   "r"(b0), "r"(b1));
}
__device__ __forceinline__ void cpa16(uint32_t d, const void* s) {
    asm volatile("cp.async.ca.shared.global [%0], [%1], 16;"
                 :: "r"(d), "l"(s) : "memory");
}
__device__ __forceinline__ void cpa_commit() {
    asm volatile("cp.async.commit_group;" ::: "memory");
}
__device__ __forceinline__ void pack2h(float a, float b, __half* dst) {
    *(__half2*)dst = __halves2half2(__float2half_rn(a), __float2half_rn(b));
}

// ================= fused weight fp32 -> fp16 (all 4 mats, 1 launch) ===========
__global__ void cvt_all(const float* __restrict__ s0, const float* __restrict__ s1,
                        const float* __restrict__ s2, const float* __restrict__ s3,
                        __half* __restrict__ dst) {
    const size_t e0 = 12582912, e1 = 16777216, e2 = 33554432, e3 = 50331648;
    size_t i = (size_t)blockIdx.x * blockDim.x + threadIdx.x;
    size_t stride = (size_t)gridDim.x * blockDim.x;
    for (; i < e3; i += stride) {
        const float* src; size_t j;
        if (i < e0)      { src = s0; j = i; }
        else if (i < e1) { src = s1; j = i - e0; }
        else if (i < e2) { src = s2; j = i - e1; }
        else             { src = s3; j = i - e2; }
        float4 v = ((const float4*)src)[j];
        ((__half2*)dst)[i * 2]     = __halves2half2(__float2half_rn(v.x),
                                                    __float2half_rn(v.y));
        ((__half2*)dst)[i * 2 + 1] = __halves2half2(__float2half_rn(v.z),
                                                    __float2half_rn(v.w));
    }
}

// ================= lora-A fp32 -> fp16 (4 tensors, 1 launch) ==================
__global__ void cvt_A(const float* __restrict__ a0, const float* __restrict__ a1,
                      const float* __restrict__ a2, const float* __restrict__ a3,
                      __half* __restrict__ dst) {
    const size_t e0 = 131072, e1 = 262144, e2 = 393216, e3 = 917504; // float4 units
    size_t i = (size_t)blockIdx.x * blockDim.x + threadIdx.x;
    size_t stride = (size_t)gridDim.x * blockDim.x;
    for (; i < e3; i += stride) {
        const float* src; size_t j;
        if (i < e0)      { src = a0; j = i; }
        else if (i < e1) { src = a1; j = i - e0; }
        else if (i < e2) { src = a2; j = i - e1; }
        else             { src = a3; j = i - e2; }
        float4 v = ((const float4*)src)[j];
        ((__half2*)dst)[i * 2]     = __halves2half2(__float2half_rn(v.x),
                                                    __float2half_rn(v.y));
        ((__half2*)dst)[i * 2 + 1] = __halves2half2(__float2half_rn(v.z),
                                                    __float2half_rn(v.w));
    }
}

// ================= fused LayerNorm + fp16 plane + lora-u (fp16 A) =============
__global__ void ln_fused(const float* __restrict__ x, const float* __restrict__ g,
                         const float* __restrict__ b, const __half* __restrict__ Ah,
                         const int* __restrict__ map,
                         __half* __restrict__ hp, float* __restrict__ u) {
    __shared__ float row[DIM];
    __shared__ float rs[8], rs2[8];
    int t = blockIdx.x;
    int tid = threadIdx.x, lane = tid & 31, warp = tid >> 5;
    const float4* x4 = (const float4*)(x + (size_t)t * DIM);
    float4* row4 = (float4*)row;
    float s = 0.f, s2 = 0.f;
    #pragma unroll
    for (int p = 0; p < 4; p++) {
        int i = tid + p * 256;
        float4 v = x4[i];
        row4[i] = v;
        s += v.x + v.y + v.z + v.w;
        s2 += v.x * v.x + v.y * v.y + v.z * v.z + v.w * v.w;
    }
    #pragma unroll
    for (int o = 16; o; o >>= 1) {
        s  += __shfl_xor_sync(0xffffffffu, s,  o);
        s2 += __shfl_xor_sync(0xffffffffu, s2, o);
    }
    if (!lane) { rs[warp] = s; rs2[warp] = s2; }
    __syncthreads();
    s = 0.f; s2 = 0.f;
    #pragma unroll
    for (int w = 0; w < 8; w++) { s += rs[w]; s2 += rs2[w]; }
    float mean = s * (1.f / DIM);
    float var  = s2 * (1.f / DIM) - mean * mean;
    float rstd = rsqrtf(var + 1e-5f);
    __half* hr = hp + (size_t)t * DIM;
    const float4* g4 = (const float4*)g;
    const float4* b4 = (const float4*)b;
    #pragma unroll
    for (int p = 0; p < 4; p++) {
        int i = tid + p * 256;
        float4 v = row4[i], gv = g4[i], bv = b4[i];
        float4 nv;
        nv.x = (v.x - mean) * rstd * gv.x + bv.x;
        nv.y = (v.y - mean) * rstd * gv.y + bv.y;
        nv.z = (v.z - mean) * rstd * gv.z + bv.z;
        nv.w = (v.w - mean) * rstd * gv.w + bv.w;
        pack2h(nv.x, nv.y, hr + i * 4);
        pack2h(nv.z, nv.w, hr + i * 4 + 2);
        row4[i] = nv;
    }
    __syncthreads();
    int a = map[t];
    #pragma unroll
    for (int rr = 0; rr < 2; rr++) {
        int r = warp * 2 + rr;
        const __half2* ar = (const __half2*)(Ah + ((size_t)a * LR + r) * DIM);
        float acc = 0.f;
        #pragma unroll
        for (int p = 0; p < 32; p++) {
            int i = lane + p * 32;
            float2 a0 = __half22float2(ar[i * 2]);
            float2 a1 = __half22float2(ar[i * 2 + 1]);
            float4 xv = row4[i];
            acc += a0.x * xv.x + a0.y * xv.y + a1.x * xv.z + a1.y * xv.w;
        }
        #pragma unroll
        for (int o = 16; o; o >>= 1) acc += __shfl_xor_sync(0xffffffffu, acc, o);
        if (!lane) u[t * LR + r] = acc;
    }
}

// ================= lora-u from fp16 plane, fp16 A, smem-staged ================
__global__ void lora_u_smem_h(const __half* __restrict__ x,
                              const __half* __restrict__ Ah,
                              const int* __restrict__ map,
                              float* __restrict__ u, int K) {
    extern __shared__ float srow[];
    int t = blockIdx.x;
    int tid = threadIdx.x, lane = tid & 31, warp = tid >> 5;
    const __half2* x2 = (const __half2*)(x + (size_t)t * K);
    int n2 = K >> 1;
    for (int i = tid; i < n2; i += 256)
        ((float2*)srow)[i] = __half22float2(x2[i]);
    __syncthreads();
    int a = map[t];
    const float4* s4 = (const float4*)srow;
    int n4 = K >> 2;
    #pragma unroll
    for (int rr = 0; rr < 2; rr++) {
        int r = warp * 2 + rr;
        const __half2* ar = (const __half2*)(Ah + ((size_t)a * LR + r) * K);
        float acc = 0.f;
        for (int i = lane; i < n4; i += 32) {
            float2 a0 = __half22float2(ar[i * 2]);
            float2 a1 = __half22float2(ar[i * 2 + 1]);
            float4 xv = s4[i];
            acc += a0.x * xv.x + a0.y * xv.y + a1.x * xv.z + a1.y * xv.w;
        }
        #pragma unroll
        for (int o = 16; o; o >>= 1) acc += __shfl_xor_sync(0xffffffffu, acc, o);
        if (!lane) u[t * LR + r] = acc;
    }
}

// ================= tensor-core GEMM (fp16 x fp16, k-chunk 64, 2-stage) ========
#define BM 128
#define BN 128
#define RSTR 72                       // smem row stride in halves (144 B)
#define PLANE (128 * RSTR * 2)        // 18432 B per plane
#define STAGE_B (2 * PLANE)           // A | W = 36864
#define SOFF_BIAS  128
#define SOFF_STAGE 1024
#define SMEM_G (SOFF_STAGE + 2 * STAGE_B)   // 74752

__device__ __forceinline__ float dot16(const float* u, const float* b) {
    float s = 0.f;
    #pragma unroll
    for (int r = 0; r < 16; r++) s = fmaf(u[r], b[r], s);
    return s;
}

__device__ __forceinline__ void issue_chunk(
        const __half* __restrict__ Ah, const __half* __restrict__ W,
        int m0, int n0, int K, int c, uint32_t sdst, int tid) {
    int k0 = c * 64;
    #pragma unroll
    for (int p = 0; p < 4; p++) {
        int idx = tid + p * 256;
        int row = idx >> 3, seg = idx & 7;
        uint32_t d = sdst + row * (RSTR * 2) + seg * 16;
        cpa16(d,         Ah + (size_t)(m0 + row) * K + k0 + seg * 8);
        cpa16(d + PLANE, W  + (size_t)(n0 + row) * K + k0 + seg * 8);
    }
    cpa_commit();
}

__global__ void __launch_bounds__(256, 2)
tc_gemm(const __half* __restrict__ Ah, const __half* __restrict__ W,
        const float* __restrict__ bias, const float* __restrict__ u,
        const float* __restrict__ Bl, const int* __restrict__ map,
        const float* __restrict__ resid, float* __restrict__ C,
        __half* __restrict__ hOut, int N, int K, int relu) {
    extern __shared__ __align__(1024) char smem[];
    uint32_t sbase = smem_u32(smem);
    int tid = threadIdx.x;
    int lane = tid & 31, warp = tid >> 5;
    int wm = warp >> 2, wn = warp & 3;
    int n0 = blockIdx.x * BN;
    int m0 = blockIdx.y * BM;

    if (tid < BN) ((float*)(smem + SOFF_BIAS))[tid] = bias[n0 + tid];

    float acc[4][4][4];
    #pragma unroll
    for (int f = 0; f < 4; f++)
        #pragma unroll
        for (int g = 0; g < 4; g++)
            #pragma unroll
            for (int e = 0; e < 4; e++) acc[f][g][e] = 0.f;

    int nCh = K >> 6;
    issue_chunk(Ah, W, m0, n0, K, 0, sbase + SOFF_STAGE, tid);
    if (nCh > 1)
        issue_chunk(Ah, W, m0, n0, K, 1, sbase + SOFF_STAGE + STAGE_B, tid);

    int lane15 = lane & 15, laneHalf = lane >> 4;
    int grp = lane >> 2, tig = lane & 3;

    int stage = 0;
    for (int c = 0; c < nCh; c++) {
        if (c + 1 < nCh)
            asm volatile("cp.async.wait_group 1;" ::: "memory");
        else
            asm volatile("cp.async.wait_group 0;" ::: "memory");
        __syncthreads();

        uint32_t base = sbase + SOFF_STAGE + stage * STAGE_B;
        #pragma unroll
        for (int ks = 0; ks < 4; ks++) {
            uint32_t af[4][4];
            int koffA = ks * 16 + laneHalf * 8;
            #pragma unroll
            for (int f = 0; f < 4; f++) {
                int row = wm * 64 + f * 16 + lane15;
                ldmx4(af[f], base + row * (RSTR * 2) + koffA * 2);
            }
            #pragma unroll
            for (int g = 0; g < 4; g++) {
                int n = wn * 32 + g * 8 + grp;
                uint32_t bd = base + PLANE + n * (RSTR * 2)
                            + (ks * 16 + tig * 2) * 2;
                uint32_t w0 = lds32(bd), w1 = lds32(bd + 16);
                #pragma unroll
                for (int f = 0; f < 4; f++)
                    mmaf16(acc[f][g], af[f], w0, w1);
            }
        }
        __syncthreads();
        if (c + 2 < nCh)
            issue_chunk(Ah, W, m0, n0, K, c + 2,
                        sbase + SOFF_STAGE + stage * STAGE_B, tid);
        stage ^= 1;
    }

    // ---- stage lora-B slice into SMEM (overlays stages) ----
    float* Bs = (float*)(smem + SOFF_STAGE);
    for (int i = tid; i < 4096; i += 256) {
        int a   = i >> 9;
        int rem = i & 511;
        int nl  = rem >> 2;
        int sg  = rem & 3;
        float4 v = *(const float4*)(Bl + ((size_t)a * N + n0 + nl) * LR + sg * 4);
        *(float4*)(Bs + ((size_t)((a << 7) + nl)) * LR + sg * 4) = v;
    }
    __syncthreads();

    const float* biasS = (const float*)(smem + SOFF_BIAS);
    #pragma unroll
    for (int f = 0; f < 4; f++) {
        int r0 = m0 + wm * 64 + f * 16 + grp;
        int r1 = r0 + 8;
        int a0 = map[r0], a1 = map[r1];
        float u0[16], u1[16];
        {
            const float4* p0 = (const float4*)(u + (size_t)r0 * LR);
            const float4* p1 = (const float4*)(u + (size_t)r1 * LR);
            #pragma unroll
            for (int q = 0; q < 4; q++) {
                float4 v0 = p0[q], v1 = p1[q];
                u0[q*4+0]=v0.x; u0[q*4+1]=v0.y; u0[q*4+2]=v0.z; u0[q*4+3]=v0.w;
                u1[q*4+0]=v1.x; u1[q*4+1]=v1.y; u1[q*4+2]=v1.z; u1[q*4+3]=v1.w;
            }
        }
        #pragma unroll
        for (int g = 0; g < 4; g++) {
            int nl = wn * 32 + g * 8 + tig * 2;
            float v00 = acc[f][g][0] + biasS[nl]
                      + dot16(u0, Bs + ((size_t)((a0 << 7) + nl)) * LR);
            float v01 = acc[f][g][1] + biasS[nl + 1]
                      + dot16(u0, Bs + ((size_t)((a0 << 7) + nl + 1)) * LR);
            float v10 = acc[f][g][2] + biasS[nl]
                      + dot16(u1, Bs + ((size_t)((a1 << 7) + nl)) * LR);
            float v11 = acc[f][g][3] + biasS[nl + 1]
                      + dot16(u1, Bs + ((size_t)((a1 << 7) + nl + 1)) * LR);
            size_t o0 = (size_t)r0 * N + n0 + nl;
            size_t o1 = (size_t)r1 * N + n0 + nl;
            if (resid) {
                float2 q0 = *(const float2*)(resid + o0);
                float2 q1 = *(const float2*)(resid + o1);
                v00 += q0.x; v01 += q0.y; v10 += q1.x; v11 += q1.y;
            }
            if (relu) {
                v00 = fmaxf(v00, 0.f); v01 = fmaxf(v01, 0.f);
                v10 = fmaxf(v10, 0.f); v11 = fmaxf(v11, 0.f);
            }
            if (C) {
                *(float2*)(C + o0) = make_float2(v00, v01);
                *(float2*)(C + o1) = make_float2(v10, v11);
            }
            if (hOut) {
                pack2h(v00, v01, hOut + o0);
                pack2h(v10, v11, hOut + o1);
            }
        }
    }
}

// ================= attention: flash online-softmax, TQ=32, all-MMA ============
#define TQ 32
// smem: qh 32x136h (8704) | kc 64x136h (17408) | vc 64x136h (17408)
//       scb 32x64 f (8192) | pt 64x40h (5120) | m/l/f 3x32 f (384)
#define ATT_QH  0
#define ATT_KC  8704
#define ATT_VC  26112
#define ATT_SCB 43520
#define ATT_PT  51712
#define ATT_M   56832
#define ATT_L   56960
#define ATT_F   57088
#define ATTN_SMEM 57216

__global__ void __launch_bounds__(256, 2)
attn7_kernel(const __half* __restrict__ qkvh, __half* __restrict__ hp) {
    extern __shared__ __align__(1024) char smemA[];
    __half* qh  = (__half*)(smemA + ATT_QH);
    float*  scb = (float*)(smemA + ATT_SCB);
    __half* pt  = (__half*)(smemA + ATT_PT);
    float*  mrow = (float*)(smemA + ATT_M);
    float*  lrow = (float*)(smemA + ATT_L);
    float*  frow = (float*)(smemA + ATT_F);
    int qt = blockIdx.x, h = blockIdx.y, bb = blockIdx.z;
    int q0 = qt * TQ;
    int tid = threadIdx.x, lane = tid & 31, warp = tid >> 5;
    int lane15 = lane & 15, laneHalf = lane >> 4;
    int grp = lane >> 2, tig = lane & 3;
    const size_t base = (size_t)bb * SEQ * H3;
    const float scale = 0.08838834764831845f;
    uint32_t qaddr = smem_u32(qh);
    uint32_t kcaddr = smem_u32(smemA + ATT_KC);
    uint32_t vcaddr = smem_u32(smemA + ATT_VC);
    uint32_t ptaddr = smem_u32(pt);

    if (tid < TQ) { mrow[tid] = -1e30f; lrow[tid] = 0.f; }

    // stage Q tile via cp.async (32 rows x 16 segs = 2 per thread)
    #pragma unroll
    for (int p = 0; p < 2; p++) {
        int idx = tid + p * 256;
        int r = idx >> 4, seg = idx & 15;
        cpa16(qaddr + r * 272 + seg * 16,
              qkvh + base + (size_t)(q0 + r) * H3 + h * HD + seg * 8);
    }
    cpa_commit();
    asm volatile("cp.async.wait_group 0;" ::: "memory");
    __syncthreads();

    float acc[2][2][4];
    #pragma unroll
    for (int mt = 0; mt < 2; mt++)
        #pragma unroll
        for (int hh = 0; hh < 2; hh++)
            #pragma unroll
            for (int e = 0; e < 4; e++) acc[mt][hh][e] = 0.f;
    int nkmax = q0 + TQ;

    for (int kb = 0; kb < nkmax; kb += 64) {
        __syncthreads();     // kc/vc/pt reuse: prior chunk's MMAs complete
        #pragma unroll
        for (int p = 0; p < 4; p++) {
            int idx = tid + p * 256;
            int r = idx >> 4, seg = idx & 15;
            uint32_t off = (uint32_t)(r * 272 + seg * 16);
            if (kb + r < nkmax) {
                const __half* src = qkvh + base + (size_t)(kb + r) * H3
                                  + h * HD + seg * 8;
                cpa16(kcaddr + off, src + DIM);
                cpa16(vcaddr + off, src + 2 * DIM);
            } else {
                *(uint4*)(smemA + ATT_VC + off) = make_uint4(0, 0, 0, 0);
            }
        }
        cpa_commit();
        asm volatile("cp.async.wait_group 0;" ::: "memory");
        __syncthreads();

        // scores: warp owns 8 keys; two q-tiles (mt)
        #pragma unroll
        for (int mt = 0; mt < 2; mt++) {
            float sacc[4] = {0.f, 0.f, 0.f, 0.f};
            #pragma unroll
            for (int ks = 0; ks < 8; ks++) {
                uint32_t qf[4];
                ldmx4(qf, qaddr + (mt * 16 + lane15) * 272
                          + (ks * 16 + laneHalf * 8) * 2);
                uint32_t bd = kcaddr + (warp * 8 + grp) * 272
                            + (ks * 16 + tig * 2) * 2;
                uint32_t w0 = lds32(bd), w1 = lds32(bd + 16);
                mmaf16(sacc, qf, w0, w1);
            }
            int kl = warp * 8 + tig * 2;
            int kcol = kb + kl;
            int r0 = mt * 16 + grp, r1 = r0 + 8;
            scb[r0 * 64 + kl]     = (kcol     <= q0 + r0) ? sacc[0] * scale : -1e30f;
            scb[r0 * 64 + kl + 1] = (kcol + 1 <= q0 + r0) ? sacc[1] * scale : -1e30f;
            scb[r1 * 64 + kl]     = (kcol     <= q0 + r1) ? sacc[2] * scale : -1e30f;
            scb[r1 * 64 + kl + 1] = (kcol + 1 <= q0 + r1) ? sacc[3] * scale : -1e30f;
        }
        __syncthreads();

        // online softmax: warp handles rows warp + 8*rr (4 rows)
        #pragma unroll
        for (int rr = 0; rr < 4; rr++) {
            int r = warp + rr * 8;
            float s0 = scb[r * 64 + lane], s1 = scb[r * 64 + lane + 32];
            float mc = fmaxf(s0, s1);
            #pragma unroll
            for (int o = 16; o; o >>= 1)
                mc = fmaxf(mc, __shfl_xor_sync(0xffffffffu, mc, o));
            float mold = mrow[r];
            float newm = fmaxf(mold, mc);
            float p0 = __expf(s0 - newm), p1 = __expf(s1 - newm);
            pt[lane * 40 + r]        = __float2half(p0);
            pt[(lane + 32) * 40 + r] = __float2half(p1);
            float ls = p0 + p1;
            #pragma unroll
            for (int o = 16; o; o >>= 1) ls += __shfl_xor_sync(0xffffffffu, ls, o);
            if (!lane) {
                float f = __expf(mold - newm);
                lrow[r] = lrow[r] * f + ls;
                mrow[r] = newm;
                frow[r] = f;
            }
        }
        __syncthreads();

        // rescale + PV MMAs: warp owns dims [warp*16, +16)
        #pragma unroll
        for (int mt = 0; mt < 2; mt++) {
            float f0 = frow[mt * 16 + grp], f1 = frow[mt * 16 + grp + 8];
            #pragma unroll
            for (int hh = 0; hh < 2; hh++) {
                acc[mt][hh][0] *= f0; acc[mt][hh][1] *= f0;
                acc[mt][hh][2] *= f1; acc[mt][hh][3] *= f1;
            }
        }
        #pragma unroll
        for (int ks = 0; ks < 4; ks++) {
            uint32_t tB[4];
            ldmx4t(tB, vcaddr + (ks * 16 + lane15) * 272
                       + (warp * 16 + laneHalf * 8) * 2);
            #pragma unroll
            for (int mt = 0; mt < 2; mt++) {
                uint32_t tA[4];
                ldmx4t(tA, ptaddr + (ks * 16 + lane15) * 80
                           + (mt * 16 + laneHalf * 8) * 2);
                uint32_t a[4] = { tA[0], tA[2], tA[1], tA[3] };
                mmaf16(acc[mt][0], a, tB[0], tB[1]);
                mmaf16(acc[mt][1], a, tB[2], tB[3]);
            }
        }
    }
    __syncthreads();

    // epilogue
    #pragma unroll
    for (int mt = 0; mt < 2; mt++) {
        float iv0 = 1.f / lrow[mt * 16 + grp];
        float iv1 = 1.f / lrow[mt * 16 + grp + 8];
        int dbase = warp * 16 + tig * 2;
        size_t o00 = ((size_t)bb * SEQ + q0 + mt * 16 + grp) * DIM + h * HD + dbase;
        size_t o10 = ((size_t)bb * SEQ + q0 + mt * 16 + grp + 8) * DIM + h * HD + dbase;
        pack2h(acc[mt][0][0] * iv0, acc[mt][0][1] * iv0, hp + o00);
        pack2h(acc[mt][0][2] * iv1, acc[mt][0][3] * iv1, hp + o10);
        pack2h(acc[mt][1][0] * iv0, acc[mt][1][1] * iv0, hp + o00 + 8);
        pack2h(acc[mt][1][2] * iv1, acc[mt][1][3] * iv1, hp + o10 + 8);
    }
}

// ---------------- launch ------------------------------------------------------
extern "C" void kernel_launch(void* const* d_in, const int* in_sizes, int n_in,
                              void* d_out, int out_size) {
    const float* x    = (const float*)d_in[0];
    const int*   map  = (const int*)  d_in[1];
    const float* Wqkv = (const float*)d_in[2];
    const float* bqkv = (const float*)d_in[3];
    const float* Wout = (const float*)d_in[4];
    const float* bout = (const float*)d_in[5];
    const float* Wfc1 = (const float*)d_in[6];
    const float* bfc1 = (const float*)d_in[7];
    const float* Wfc2 = (const float*)d_in[8];
    const float* bfc2 = (const float*)d_in[9];
    const float* ln1g = (const float*)d_in[10];
    const float* ln1b = (const float*)d_in[11];
    const float* ln2g = (const float*)d_in[12];
    const float* ln2b = (const float*)d_in[13];
    const float* Aqkv = (const float*)d_in[14];
    const float* Bqkv = (const float*)d_in[15];
    const float* Aout = (const float*)d_in[16];
    const float* Bout = (const float*)d_in[17];
    const float* Afc1 = (const float*)d_in[18];
    const float* Bfc1 = (const float*)d_in[19];
    const float* Afc2 = (const float*)d_in[20];
    const float* Bfc2 = (const float*)d_in[21];
    float* out = (float*)d_out;

    float *p_res2, *p_u;
    __half *p_Wh, *p_AS, *p_AL, *p_Ah;
    cudaGetSymbolAddress((void**)&p_res2, g_res2);
    cudaGetSymbolAddress((void**)&p_u,    g_u);
    cudaGetSymbolAddress((void**)&p_Wh,   g_Wh);
    cudaGetSymbolAddress((void**)&p_AS,   g_AS);
    cudaGetSymbolAddress((void**)&p_AL,   g_AL);
    cudaGetSymbolAddress((void**)&p_Ah,   g_Ah);
    __half* p_qkvh = p_AL;   // fp16 qkv plane reuses the large activation plane

    cudaFuncSetAttribute(tc_gemm, cudaFuncAttributeMaxDynamicSharedMemorySize, SMEM_G);
    cudaFuncSetAttribute(attn7_kernel, cudaFuncAttributeMaxDynamicSharedMemorySize,
                         ATTN_SMEM);
    cudaFuncSetAttribute(lora_u_smem_h, cudaFuncAttributeMaxDynamicSharedMemorySize,
                         FFN_D * 4);

    // ---- weights + lora-A -> fp16 ----
    cvt_all<<<8192, 256>>>(Wqkv, Wout, Wfc1, Wfc2, p_Wh);
    cvt_A<<<1024, 256>>>(Aqkv, Aout, Afc1, Afc2, p_Ah);

    // ---- attention block ----
    ln_fused<<<NT, 256>>>(x, ln1g, ln1b, p_Ah + AOFF_QKV, map, p_AS, p_u);
    tc_gemm<<<dim3(H3 / BN, NT / BM), 256, SMEM_G>>>(
        p_AS, p_Wh + WOFF_QKV, bqkv, p_u, Bqkv, map,
        nullptr, nullptr, p_qkvh, H3, DIM, 0);
    attn7_kernel<<<dim3(SEQ / TQ, NH, 2), 256, ATTN_SMEM>>>(p_qkvh, p_AS);
    lora_u_smem_h<<<NT, 256, DIM * 4>>>(p_AS, p_Ah + AOFF_OUT, map, p_u, DIM);
    tc_gemm<<<dim3(DIM / BN, NT / BM), 256, SMEM_G>>>(
        p_AS, p_Wh + WOFF_OUT, bout, p_u, Bout, map,
        x, p_res2, nullptr, DIM, DIM, 0);
    // ---- FFN block ----
    ln_fused<<<NT, 256>>>(p_res2, ln2g, ln2b, p_Ah + AOFF_FC1, map, p_AS, p_u);
    tc_gemm<<<dim3(FFN_D / BN, NT / BM), 256, SMEM_G>>>(
        p_AS, p_Wh + WOFF_FC1, bfc1, p_u, Bfc1, map,
        nullptr, nullptr, p_AL, FFN_D, DIM, 1);
    lora_u_smem_h<<<NT, 256, FFN_D * 4>>>(p_AL, p_Ah + AOFF_FC2, map, p_u, FFN_D);
    tc_gemm<<<dim3(DIM / BN, NT / BM), 256, SMEM_G>>>(
        p_AL, p_Wh + WOFF_FC2, bfc2, p_u, Bfc2, map,
        p_res2, out, nullptr, DIM, FFN_D, 0);
}

// round 17
// speedup vs baseline: 1.0423x; 1.0423x over previous
#include <cuda_runtime.h>
#include <cuda_fp16.h>
#include <cstdint>
#include <cstddef>

#define DIM   4096
#define H3    12288
#define FFN_D 16384
#define NT    2048      // total tokens = 2*1024
#define LR    16        // lora rank
#define SEQ   1024
#define NH    32
#define HD    128
#define NA    8

// ---------------- scratch (device globals; no allocations allowed) ----------
__device__ float g_res2[(size_t)NT * DIM];
__device__ float g_u   [(size_t)NT * LR];

// fp16 weight plane + fp16 activation planes
#define WOFF_QKV 0
#define WOFF_OUT 50331648u
#define WOFF_FC1 67108864u
#define WOFF_FC2 134217728u
#define W_TOTAL  201326592u
__device__ __half g_Wh [W_TOTAL];
__device__ __half g_AS [(size_t)NT * DIM];
__device__ __half g_AL [(size_t)NT * FFN_D];   // doubles as fp16 qkv plane

// fp16 lora-A planes: qkv | out | fc1 (each 8*16*4096) then fc2 (8*16*16384)
#define AOFF_QKV 0
#define AOFF_OUT 524288u
#define AOFF_FC1 1048576u
#define AOFF_FC2 1572864u
#define A_TOTAL  3670016u
__device__ __half g_Ah [A_TOTAL];

// ================= helpers ===================================================
__device__ __forceinline__ uint32_t smem_u32(const void* p) {
    uint32_t a;
    asm("{ .reg .u64 t; cvta.to.shared.u64 t, %1; cvt.u32.u64 %0, t; }"
        : "=r"(a) : "l"(p));
    return a;
}
__device__ __forceinline__ void ldmx4(uint32_t* r, uint32_t addr) {
    asm volatile("ldmatrix.sync.aligned.m8n8.x4.shared.b16 {%0,%1,%2,%3}, [%4];"
                 : "=r"(r[0]), "=r"(r[1]), "=r"(r[2]), "=r"(r[3]) : "r"(addr));
}
__device__ __forceinline__ void ldmx4t(uint32_t* r, uint32_t addr) {
    asm volatile("ldmatrix.sync.aligned.m8n8.x4.trans.shared.b16 {%0,%1,%2,%3}, [%4];"
                 : "=r"(r[0]), "=r"(r[1]), "=r"(r[2]), "=r"(r[3]) : "r"(addr));
}
__device__ __forceinline__ uint32_t lds32(uint32_t addr) {
    uint32_t v;
    asm volatile("ld.shared.b32 %0, [%1];" : "=r"(v) : "r"(addr));
    return v;
}
__device__ __forceinline__ void mmaf16(float* d, const uint32_t* a,
                                       uint32_t b0, uint32_t b1) {
    asm volatile("mma.sync.aligned.m16n8k16.row.col.f32.f16.f16.f32 "
                 "{%0,%1,%2,%3}, {%4,%5,%6,%7}, {%8,%9}, {%0,%1,%2,%3};"
                 : "+f"(d[0]), "+f"(d[1]), "+f"(d[2]), "+f"(d[3])
                 : "r"(a[0]), "r"(a[1]), "r"(a[2]), "r"(a[3]),
                   "r"(b0), "r"(b1));
}
__device__ __forceinline__ void cpa16(uint32_t d, const void* s) {
    asm volatile("cp.async.ca.shared.global [%0], [%1], 16;"
                 :: "r"(d), "l"(s) : "memory");
}
__device__ __forceinline__ void cpa_commit() {
    asm volatile("cp.async.commit_group;" ::: "memory");
}
__device__ __forceinline__ void pack2h(float a, float b, __half* dst) {
    *(__half2*)dst = __halves2half2(__float2half_rn(a), __float2half_rn(b));
}

// ================= fused weight fp32 -> fp16 (all 4 mats, 1 launch) ===========
__global__ void cvt_all(const float* __restrict__ s0, const float* __restrict__ s1,
                        const float* __restrict__ s2, const float* __restrict__ s3,
                        __half* __restrict__ dst) {
    const size_t e0 = 12582912, e1 = 16777216, e2 = 33554432, e3 = 50331648;
    size_t i = (size_t)blockIdx.x * blockDim.x + threadIdx.x;
    size_t stride = (size_t)gridDim.x * blockDim.x;
    for (; i < e3; i += stride) {
        const float* src; size_t j;
        if (i < e0)      { src = s0; j = i; }
        else if (i < e1) { src = s1; j = i - e0; }
        else if (i < e2) { src = s2; j = i - e1; }
        else             { src = s3; j = i - e2; }
        float4 v = ((const float4*)src)[j];
        ((__half2*)dst)[i * 2]     = __halves2half2(__float2half_rn(v.x),
                                                    __float2half_rn(v.y));
        ((__half2*)dst)[i * 2 + 1] = __halves2half2(__float2half_rn(v.z),
                                                    __float2half_rn(v.w));
    }
}

// ================= lora-A fp32 -> fp16 (4 tensors, 1 launch) ==================
__global__ void cvt_A(const float* __restrict__ a0, const float* __restrict__ a1,
                      const float* __restrict__ a2, const float* __restrict__ a3,
                      __half* __restrict__ dst) {
    const size_t e0 = 131072, e1 = 262144, e2 = 393216, e3 = 917504; // float4 units
    size_t i = (size_t)blockIdx.x * blockDim.x + threadIdx.x;
    size_t stride = (size_t)gridDim.x * blockDim.x;
    for (; i < e3; i += stride) {
        const float* src; size_t j;
        if (i < e0)      { src = a0; j = i; }
        else if (i < e1) { src = a1; j = i - e0; }
        else if (i < e2) { src = a2; j = i - e1; }
        else             { src = a3; j = i - e2; }
        float4 v = ((const float4*)src)[j];
        ((__half2*)dst)[i * 2]     = __halves2half2(__float2half_rn(v.x),
                                                    __float2half_rn(v.y));
        ((__half2*)dst)[i * 2 + 1] = __halves2half2(__float2half_rn(v.z),
                                                    __float2half_rn(v.w));
    }
}

// ================= fused LayerNorm + fp16 plane + lora-u (fp16 A) =============
__global__ void ln_fused(const float* __restrict__ x, const float* __restrict__ g,
                         const float* __restrict__ b, const __half* __restrict__ Ah,
                         const int* __restrict__ map,
                         __half* __restrict__ hp, float* __restrict__ u) {
    __shared__ float row[DIM];
    __shared__ float rs[8], rs2[8];
    int t = blockIdx.x;
    int tid = threadIdx.x, lane = tid & 31, warp = tid >> 5;
    const float4* x4 = (const float4*)(x + (size_t)t * DIM);
    float4* row4 = (float4*)row;
    float s = 0.f, s2 = 0.f;
    #pragma unroll
    for (int p = 0; p < 4; p++) {
        int i = tid + p * 256;
        float4 v = x4[i];
        row4[i] = v;
        s += v.x + v.y + v.z + v.w;
        s2 += v.x * v.x + v.y * v.y + v.z * v.z + v.w * v.w;
    }
    #pragma unroll
    for (int o = 16; o; o >>= 1) {
        s  += __shfl_xor_sync(0xffffffffu, s,  o);
        s2 += __shfl_xor_sync(0xffffffffu, s2, o);
    }
    if (!lane) { rs[warp] = s; rs2[warp] = s2; }
    __syncthreads();
    s = 0.f; s2 = 0.f;
    #pragma unroll
    for (int w = 0; w < 8; w++) { s += rs[w]; s2 += rs2[w]; }
    float mean = s * (1.f / DIM);
    float var  = s2 * (1.f / DIM) - mean * mean;
    float rstd = rsqrtf(var + 1e-5f);
    __half* hr = hp + (size_t)t * DIM;
    const float4* g4 = (const float4*)g;
    const float4* b4 = (const float4*)b;
    #pragma unroll
    for (int p = 0; p < 4; p++) {
        int i = tid + p * 256;
        float4 v = row4[i], gv = g4[i], bv = b4[i];
        float4 nv;
        nv.x = (v.x - mean) * rstd * gv.x + bv.x;
        nv.y = (v.y - mean) * rstd * gv.y + bv.y;
        nv.z = (v.z - mean) * rstd * gv.z + bv.z;
        nv.w = (v.w - mean) * rstd * gv.w + bv.w;
        pack2h(nv.x, nv.y, hr + i * 4);
        pack2h(nv.z, nv.w, hr + i * 4 + 2);
        row4[i] = nv;
    }
    __syncthreads();
    int a = map[t];
    #pragma unroll
    for (int rr = 0; rr < 2; rr++) {
        int r = warp * 2 + rr;
        const __half2* ar = (const __half2*)(Ah + ((size_t)a * LR + r) * DIM);
        float acc = 0.f;
        #pragma unroll
        for (int p = 0; p < 32; p++) {
            int i = lane + p * 32;
            float2 a0 = __half22float2(ar[i * 2]);
            float2 a1 = __half22float2(ar[i * 2 + 1]);
            float4 xv = row4[i];
            acc += a0.x * xv.x + a0.y * xv.y + a1.x * xv.z + a1.y * xv.w;
        }
        #pragma unroll
        for (int o = 16; o; o >>= 1) acc += __shfl_xor_sync(0xffffffffu, acc, o);
        if (!lane) u[t * LR + r] = acc;
    }
}

// ================= lora-u from fp16 plane, fp16 A, smem-staged ================
__global__ void lora_u_smem_h(const __half* __restrict__ x,
                              const __half* __restrict__ Ah,
                              const int* __restrict__ map,
                              float* __restrict__ u, int K) {
    extern __shared__ float srow[];
    int t = blockIdx.x;
    int tid = threadIdx.x, lane = tid & 31, warp = tid >> 5;
    const __half2* x2 = (const __half2*)(x + (size_t)t * K);
    int n2 = K >> 1;
    for (int i = tid; i < n2; i += 256)
        ((float2*)srow)[i] = __half22float2(x2[i]);
    __syncthreads();
    int a = map[t];
    const float4* s4 = (const float4*)srow;
    int n4 = K >> 2;
    #pragma unroll
    for (int rr = 0; rr < 2; rr++) {
        int r = warp * 2 + rr;
        const __half2* ar = (const __half2*)(Ah + ((size_t)a * LR + r) * K);
        float acc = 0.f;
        for (int i = lane; i < n4; i += 32) {
            float2 a0 = __half22float2(ar[i * 2]);
            float2 a1 = __half22float2(ar[i * 2 + 1]);
            float4 xv = s4[i];
            acc += a0.x * xv.x + a0.y * xv.y + a1.x * xv.z + a1.y * xv.w;
        }
        #pragma unroll
        for (int o = 16; o; o >>= 1) acc += __shfl_xor_sync(0xffffffffu, acc, o);
        if (!lane) u[t * LR + r] = acc;
    }
}

// ================= tensor-core GEMM (fp16 x fp16, k-chunk 64, 2-stage) ========
#define BM 128
#define BN 128
#define RSTR 72                       // smem row stride in halves (144 B)
#define PLANE (128 * RSTR * 2)        // 18432 B per plane
#define STAGE_B (2 * PLANE)           // A | W = 36864
#define SOFF_BIAS  128
#define SOFF_STAGE 1024
#define SMEM_G (SOFF_STAGE + 2 * STAGE_B)   // 74752

__device__ __forceinline__ float dot16(const float* u, const float* b) {
    float s = 0.f;
    #pragma unroll
    for (int r = 0; r < 16; r++) s = fmaf(u[r], b[r], s);
    return s;
}

__device__ __forceinline__ void issue_chunk(
        const __half* __restrict__ Ah, const __half* __restrict__ W,
        int m0, int n0, int K, int c, uint32_t sdst, int tid) {
    int k0 = c * 64;
    #pragma unroll
    for (int p = 0; p < 4; p++) {
        int idx = tid + p * 256;
        int row = idx >> 3, seg = idx & 7;
        uint32_t d = sdst + row * (RSTR * 2) + seg * 16;
        cpa16(d,         Ah + (size_t)(m0 + row) * K + k0 + seg * 8);
        cpa16(d + PLANE, W  + (size_t)(n0 + row) * K + k0 + seg * 8);
    }
    cpa_commit();
}

__global__ void __launch_bounds__(256, 2)
tc_gemm(const __half* __restrict__ Ah, const __half* __restrict__ W,
        const float* __restrict__ bias, const float* __restrict__ u,
        const float* __restrict__ Bl, const int* __restrict__ map,
        const float* __restrict__ resid, float* __restrict__ C,
        __half* __restrict__ hOut, int N, int K, int relu) {
    extern __shared__ __align__(1024) char smem[];
    uint32_t sbase = smem_u32(smem);
    int tid = threadIdx.x;
    int lane = tid & 31, warp = tid >> 5;
    int wm = warp >> 2, wn = warp & 3;
    int n0 = blockIdx.x * BN;
    int m0 = blockIdx.y * BM;

    if (tid < BN) ((float*)(smem + SOFF_BIAS))[tid] = bias[n0 + tid];

    float acc[4][4][4];
    #pragma unroll
    for (int f = 0; f < 4; f++)
        #pragma unroll
        for (int g = 0; g < 4; g++)
            #pragma unroll
            for (int e = 0; e < 4; e++) acc[f][g][e] = 0.f;

    int nCh = K >> 6;
    issue_chunk(Ah, W, m0, n0, K, 0, sbase + SOFF_STAGE, tid);
    if (nCh > 1)
        issue_chunk(Ah, W, m0, n0, K, 1, sbase + SOFF_STAGE + STAGE_B, tid);

    int lane15 = lane & 15, laneHalf = lane >> 4;
    int grp = lane >> 2, tig = lane & 3;
    // B ldmatrix lane offset: row = wn*32 + gp*16 + ((lane>>4)&1)*8 + (lane&7),
    //                         koff = ((lane>>3)&1)*8
    uint32_t bOffL = (uint32_t)((((lane >> 4) & 1) * 8 + (lane & 7)) * (RSTR * 2)
                               + ((lane >> 3) & 1) * 16);

    int stage = 0;
    for (int c = 0; c < nCh; c++) {
        if (c + 1 < nCh)
            asm volatile("cp.async.wait_group 1;" ::: "memory");
        else
            asm volatile("cp.async.wait_group 0;" ::: "memory");
        __syncthreads();

        uint32_t base = sbase + SOFF_STAGE + stage * STAGE_B;
        uint32_t bBase = base + PLANE + wn * 32 * (RSTR * 2) + bOffL;
        #pragma unroll
        for (int ks = 0; ks < 4; ks++) {
            uint32_t af[4][4];
            int koffA = ks * 16 + laneHalf * 8;
            #pragma unroll
            for (int f = 0; f < 4; f++) {
                int row = wm * 64 + f * 16 + lane15;
                ldmx4(af[f], base + row * (RSTR * 2) + koffA * 2);
            }
            #pragma unroll
            for (int gp = 0; gp < 2; gp++) {
                uint32_t bf[4];
                ldmx4(bf, bBase + gp * 16 * (RSTR * 2) + ks * 32);
                #pragma unroll
                for (int f = 0; f < 4; f++) {
                    mmaf16(acc[f][2 * gp],     af[f], bf[0], bf[1]);
                    mmaf16(acc[f][2 * gp + 1], af[f], bf[2], bf[3]);
                }
            }
        }
        __syncthreads();
        if (c + 2 < nCh)
            issue_chunk(Ah, W, m0, n0, K, c + 2,
                        sbase + SOFF_STAGE + stage * STAGE_B, tid);
        stage ^= 1;
    }

    // ---- stage lora-B slice into SMEM (overlays stages) ----
    float* Bs = (float*)(smem + SOFF_STAGE);
    for (int i = tid; i < 4096; i += 256) {
        int a   = i >> 9;
        int rem = i & 511;
        int nl  = rem >> 2;
        int sg  = rem & 3;
        float4 v = *(const float4*)(Bl + ((size_t)a * N + n0 + nl) * LR + sg * 4);
        *(float4*)(Bs + ((size_t)((a << 7) + nl)) * LR + sg * 4) = v;
    }
    __syncthreads();

    const float* biasS = (const float*)(smem + SOFF_BIAS);
    #pragma unroll
    for (int f = 0; f < 4; f++) {
        int r0 = m0 + wm * 64 + f * 16 + grp;
        int r1 = r0 + 8;
        int a0 = map[r0], a1 = map[r1];
        float u0[16], u1[16];
        {
            const float4* p0 = (const float4*)(u + (size_t)r0 * LR);
            const float4* p1 = (const float4*)(u + (size_t)r1 * LR);
            #pragma unroll
            for (int q = 0; q < 4; q++) {
                float4 v0 = p0[q], v1 = p1[q];
                u0[q*4+0]=v0.x; u0[q*4+1]=v0.y; u0[q*4+2]=v0.z; u0[q*4+3]=v0.w;
                u1[q*4+0]=v1.x; u1[q*4+1]=v1.y; u1[q*4+2]=v1.z; u1[q*4+3]=v1.w;
            }
        }
        #pragma unroll
        for (int g = 0; g < 4; g++) {
            int nl = wn * 32 + g * 8 + tig * 2;
            float v00 = acc[f][g][0] + biasS[nl]
                      + dot16(u0, Bs + ((size_t)((a0 << 7) + nl)) * LR);
            float v01 = acc[f][g][1] + biasS[nl + 1]
                      + dot16(u0, Bs + ((size_t)((a0 << 7) + nl + 1)) * LR);
            float v10 = acc[f][g][2] + biasS[nl]
                      + dot16(u1, Bs + ((size_t)((a1 << 7) + nl)) * LR);
            float v11 = acc[f][g][3] + biasS[nl + 1]
                      + dot16(u1, Bs + ((size_t)((a1 << 7) + nl + 1)) * LR);
            size_t o0 = (size_t)r0 * N + n0 + nl;
            size_t o1 = (size_t)r1 * N + n0 + nl;
            if (resid) {
                float2 q0 = *(const float2*)(resid + o0);
                float2 q1 = *(const float2*)(resid + o1);
                v00 += q0.x; v01 += q0.y; v10 += q1.x; v11 += q1.y;
            }
            if (relu) {
                v00 = fmaxf(v00, 0.f); v01 = fmaxf(v01, 0.f);
                v10 = fmaxf(v10, 0.f); v11 = fmaxf(v11, 0.f);
            }
            if (C) {
                *(float2*)(C + o0) = make_float2(v00, v01);
                *(float2*)(C + o1) = make_float2(v10, v11);
            }
            if (hOut) {
                pack2h(v00, v01, hOut + o0);
                pack2h(v10, v11, hOut + o1);
            }
        }
    }
}

// ================= attention: flash online-softmax, TQ=32, all-MMA ============
#define TQ 32
// smem: qh 32x136h (8704) | kc 64x136h (17408) | vc 64x136h (17408)
//       scb 32x64 f (8192) | pt 64x40h (5120) | m/l/f 3x32 f (384)
#define ATT_QH  0
#define ATT_KC  8704
#define ATT_VC  26112
#define ATT_SCB 43520
#define ATT_PT  51712
#define ATT_M   56832
#define ATT_L   56960
#define ATT_F   57088
#define ATTN_SMEM 57216

__global__ void __launch_bounds__(256, 2)
attn7_kernel(const __half* __restrict__ qkvh, __half* __restrict__ hp) {
    extern __shared__ __align__(1024) char smemA[];
    __half* qh  = (__half*)(smemA + ATT_QH);
    float*  scb = (float*)(smemA + ATT_SCB);
    __half* pt  = (__half*)(smemA + ATT_PT);
    float*  mrow = (float*)(smemA + ATT_M);
    float*  lrow = (float*)(smemA + ATT_L);
    float*  frow = (float*)(smemA + ATT_F);
    int qt = blockIdx.x, h = blockIdx.y, bb = blockIdx.z;
    int q0 = qt * TQ;
    int tid = threadIdx.x, lane = tid & 31, warp = tid >> 5;
    int lane15 = lane & 15, laneHalf = lane >> 4;
    int grp = lane >> 2, tig = lane & 3;
    const size_t base = (size_t)bb * SEQ * H3;
    const float scale = 0.08838834764831845f;
    uint32_t qaddr = smem_u32(qh);
    uint32_t kcaddr = smem_u32(smemA + ATT_KC);
    uint32_t vcaddr = smem_u32(smemA + ATT_VC);
    uint32_t ptaddr = smem_u32(pt);

    if (tid < TQ) { mrow[tid] = -1e30f; lrow[tid] = 0.f; }

    // stage Q tile via cp.async (32 rows x 16 segs = 2 per thread)
    #pragma unroll
    for (int p = 0; p < 2; p++) {
        int idx = tid + p * 256;
        int r = idx >> 4, seg = idx & 15;
        cpa16(qaddr + r * 272 + seg * 16,
              qkvh + base + (size_t)(q0 + r) * H3 + h * HD + seg * 8);
    }
    cpa_commit();
    asm volatile("cp.async.wait_group 0;" ::: "memory");
    __syncthreads();

    float acc[2][2][4];
    #pragma unroll
    for (int mt = 0; mt < 2; mt++)
        #pragma unroll
        for (int hh = 0; hh < 2; hh++)
            #pragma unroll
            for (int e = 0; e < 4; e++) acc[mt][hh][e] = 0.f;
    int nkmax = q0 + TQ;

    for (int kb = 0; kb < nkmax; kb += 64) {
        __syncthreads();     // kc/vc/pt reuse: prior chunk's MMAs complete
        #pragma unroll
        for (int p = 0; p < 4; p++) {
            int idx = tid + p * 256;
            int r = idx >> 4, seg = idx & 15;
            uint32_t off = (uint32_t)(r * 272 + seg * 16);
            if (kb + r < nkmax) {
                const __half* src = qkvh + base + (size_t)(kb + r) * H3
                                  + h * HD + seg * 8;
                cpa16(kcaddr + off, src + DIM);
                cpa16(vcaddr + off, src + 2 * DIM);
            } else {
                *(uint4*)(smemA + ATT_VC + off) = make_uint4(0, 0, 0, 0);
            }
        }
        cpa_commit();
        asm volatile("cp.async.wait_group 0;" ::: "memory");
        __syncthreads();

        // scores: warp owns 8 keys; two q-tiles (mt)
        #pragma unroll
        for (int mt = 0; mt < 2; mt++) {
            float sacc[4] = {0.f, 0.f, 0.f, 0.f};
            #pragma unroll
            for (int ks = 0; ks < 8; ks++) {
                uint32_t qf[4];
                ldmx4(qf, qaddr + (mt * 16 + lane15) * 272
                          + (ks * 16 + laneHalf * 8) * 2);
                uint32_t bd = kcaddr + (warp * 8 + grp) * 272
                            + (ks * 16 + tig * 2) * 2;
                uint32_t w0 = lds32(bd), w1 = lds32(bd + 16);
                mmaf16(sacc, qf, w0, w1);
            }
            int kl = warp * 8 + tig * 2;
            int kcol = kb + kl;
            int r0 = mt * 16 + grp, r1 = r0 + 8;
            scb[r0 * 64 + kl]     = (kcol     <= q0 + r0) ? sacc[0] * scale : -1e30f;
            scb[r0 * 64 + kl + 1] = (kcol + 1 <= q0 + r0) ? sacc[1] * scale : -1e30f;
            scb[r1 * 64 + kl]     = (kcol     <= q0 + r1) ? sacc[2] * scale : -1e30f;
            scb[r1 * 64 + kl + 1] = (kcol + 1 <= q0 + r1) ? sacc[3] * scale : -1e30f;
        }
        __syncthreads();

        // online softmax: warp handles rows warp + 8*rr (4 rows)
        #pragma unroll
        for (int rr = 0; rr < 4; rr++) {
            int r = warp + rr * 8;
            float s0 = scb[r * 64 + lane], s1 = scb[r * 64 + lane + 32];
            float mc = fmaxf(s0, s1);
            #pragma unroll
            for (int o = 16; o; o >>= 1)
                mc = fmaxf(mc, __shfl_xor_sync(0xffffffffu, mc, o));
            float mold = mrow[r];
            float newm = fmaxf(mold, mc);
            float p0 = __expf(s0 - newm), p1 = __expf(s1 - newm);
            pt[lane * 40 + r]        = __float2half(p0);
            pt[(lane + 32) * 40 + r] = __float2half(p1);
            float ls = p0 + p1;
            #pragma unroll
            for (int o = 16; o; o >>= 1) ls += __shfl_xor_sync(0xffffffffu, ls, o);
            if (!lane) {
                float f = __expf(mold - newm);
                lrow[r] = lrow[r] * f + ls;
                mrow[r] = newm;
                frow[r] = f;
            }
        }
        __syncthreads();

        // rescale + PV MMAs: warp owns dims [warp*16, +16)
        #pragma unroll
        for (int mt = 0; mt < 2; mt++) {
            float f0 = frow[mt * 16 + grp], f1 = frow[mt * 16 + grp + 8];
            #pragma unroll
            for (int hh = 0; hh < 2; hh++) {
                acc[mt][hh][0] *= f0; acc[mt][hh][1] *= f0;
                acc[mt][hh][2] *= f1; acc[mt][hh][3] *= f1;
            }
        }
        #pragma unroll
        for (int ks = 0; ks < 4; ks++) {
            uint32_t tB[4];
            ldmx4t(tB, vcaddr + (ks * 16 + lane15) * 272
                       + (warp * 16 + laneHalf * 8) * 2);
            #pragma unroll
            for (int mt = 0; mt < 2; mt++) {
                uint32_t tA[4];
                ldmx4t(tA, ptaddr + (ks * 16 + lane15) * 80
                           + (mt * 16 + laneHalf * 8) * 2);
                uint32_t a[4] = { tA[0], tA[2], tA[1], tA[3] };
                mmaf16(acc[mt][0], a, tB[0], tB[1]);
                mmaf16(acc[mt][1], a, tB[2], tB[3]);
            }
        }
    }
    __syncthreads();

    // epilogue
    #pragma unroll
    for (int mt = 0; mt < 2; mt++) {
        float iv0 = 1.f / lrow[mt * 16 + grp];
        float iv1 = 1.f / lrow[mt * 16 + grp + 8];
        int dbase = warp * 16 + tig * 2;
        size_t o00 = ((size_t)bb * SEQ + q0 + mt * 16 + grp) * DIM + h * HD + dbase;
        size_t o10 = ((size_t)bb * SEQ + q0 + mt * 16 + grp + 8) * DIM + h * HD + dbase;
        pack2h(acc[mt][0][0] * iv0, acc[mt][0][1] * iv0, hp + o00);
        pack2h(acc[mt][0][2] * iv1, acc[mt][0][3] * iv1, hp + o10);
        pack2h(acc[mt][1][0] * iv0, acc[mt][1][1] * iv0, hp + o00 + 8);
        pack2h(acc[mt][1][2] * iv1, acc[mt][1][3] * iv1, hp + o10 + 8);
    }
}

// ---------------- launch ------------------------------------------------------
extern "C" void kernel_launch(void* const* d_in, const int* in_sizes, int n_in,
                              void* d_out, int out_size) {
    const float* x    = (const float*)d_in[0];
    const int*   map  = (const int*)  d_in[1];
    const float* Wqkv = (const float*)d_in[2];
    const float* bqkv = (const float*)d_in[3];
    const float* Wout = (const float*)d_in[4];
    const float* bout = (const float*)d_in[5];
    const float* Wfc1 = (const float*)d_in[6];
    const float* bfc1 = (const float*)d_in[7];
    const float* Wfc2 = (const float*)d_in[8];
    const float* bfc2 = (const float*)d_in[9];
    const float* ln1g = (const float*)d_in[10];
    const float* ln1b = (const float*)d_in[11];
    const float* ln2g = (const float*)d_in[12];
    const float* ln2b = (const float*)d_in[13];
    const float* Aqkv = (const float*)d_in[14];
    const float* Bqkv = (const float*)d_in[15];
    const float* Aout = (const float*)d_in[16];
    const float* Bout = (const float*)d_in[17];
    const float* Afc1 = (const float*)d_in[18];
    const float* Bfc1 = (const float*)d_in[19];
    const float* Afc2 = (const float*)d_in[20];
    const float* Bfc2 = (const float*)d_in[21];
    float* out = (float*)d_out;

    float *p_res2, *p_u;
    __half *p_Wh, *p_AS, *p_AL, *p_Ah;
    cudaGetSymbolAddress((void**)&p_res2, g_res2);
    cudaGetSymbolAddress((void**)&p_u,    g_u);
    cudaGetSymbolAddress((void**)&p_Wh,   g_Wh);
    cudaGetSymbolAddress((void**)&p_AS,   g_AS);
    cudaGetSymbolAddress((void**)&p_AL,   g_AL);
    cudaGetSymbolAddress((void**)&p_Ah,   g_Ah);
    __half* p_qkvh = p_AL;   // fp16 qkv plane reuses the large activation plane

    cudaFuncSetAttribute(tc_gemm, cudaFuncAttributeMaxDynamicSharedMemorySize, SMEM_G);
    cudaFuncSetAttribute(attn7_kernel, cudaFuncAttributeMaxDynamicSharedMemorySize,
                         ATTN_SMEM);
    cudaFuncSetAttribute(lora_u_smem_h, cudaFuncAttributeMaxDynamicSharedMemorySize,
                         FFN_D * 4);

    // ---- weights + lora-A -> fp16 ----
    cvt_all<<<8192, 256>>>(Wqkv, Wout, Wfc1, Wfc2, p_Wh);
    cvt_A<<<1024, 256>>>(Aqkv, Aout, Afc1, Afc2, p_Ah);

    // ---- attention block ----
    ln_fused<<<NT, 256>>>(x, ln1g, ln1b, p_Ah + AOFF_QKV, map, p_AS, p_u);
    tc_gemm<<<dim3(H3 / BN, NT / BM), 256, SMEM_G>>>(
        p_AS, p_Wh + WOFF_QKV, bqkv, p_u, Bqkv, map,
        nullptr, nullptr, p_qkvh, H3, DIM, 0);
    attn7_kernel<<<dim3(SEQ / TQ, NH, 2), 256, ATTN_SMEM>>>(p_qkvh, p_AS);
    lora_u_smem_h<<<NT, 256, DIM * 4>>>(p_AS, p_Ah + AOFF_OUT, map, p_u, DIM);
    tc_gemm<<<dim3(DIM / BN, NT / BM), 256, SMEM_G>>>(
        p_AS, p_Wh + WOFF_OUT, bout, p_u, Bout, map,
        x, p_res2, nullptr, DIM, DIM, 0);
    // ---- FFN block ----
    ln_fused<<<NT, 256>>>(p_res2, ln2g, ln2b, p_Ah + AOFF_FC1, map, p_AS, p_u);
    tc_gemm<<<dim3(FFN_D / BN, NT / BM), 256, SMEM_G>>>(
        p_AS, p_Wh + WOFF_FC1, bfc1, p_u, Bfc1, map,
        nullptr, nullptr, p_AL, FFN_D, DIM, 1);
    lora_u_smem_h<<<NT, 256, FFN_D * 4>>>(p_AL, p_Ah + AOFF_FC2, map, p_u, FFN_D);
    tc_gemm<<<dim3(DIM / BN, NT / BM), 256, SMEM_G>>>(
        p_AL, p_Wh + WOFF_FC2, bfc2, p_u, Bfc2, map,
        p_res2, out, nullptr, DIM, FFN_D, 0);
}